// round 3
// baseline (speedup 1.0000x reference)
#include <cuda_runtime.h>

#define NB 4096
#define NF 1024
#define NR 64
#define NK 32
#define ND 16
#define TB 16
#define THREADS 128
#define LOG_2PI 1.8378770664093453f

// Precomputed per-(r,k,d) coefficients:
//   inv = 1/scale, nmi = -mean/scale  packed as float4 {inv0,nmi0,inv1,nmi1}
//   layout [r][d/2][k] so lane k loads a float4 per 2 d's (coalesced 128B).
__device__ float4 g_coef4[NR * (ND / 2) * NK];
// g_c[r*K+k] = -(sum_d log scale) - 0.5*D*log(2pi)
__device__ float g_c[NR * NK];

__global__ void prep_kernel(const float* __restrict__ means,
                            const float* __restrict__ scales) {
    int id = blockIdx.x * blockDim.x + threadIdx.x;  // r*NK + k
    if (id >= NR * NK) return;
    int r = id / NK, k = id % NK;
    const float* m = means + (size_t)id * ND;   // means[r][k][d] contiguous
    const float* s = scales + (size_t)id * ND;
    float logdet = 0.f;
#pragma unroll
    for (int d2 = 0; d2 < ND / 2; d2++) {
        float s0 = s[2 * d2], s1 = s[2 * d2 + 1];
        float i0 = 1.0f / s0, i1 = 1.0f / s1;
        float4 c;
        c.x = i0; c.y = -m[2 * d2] * i0;
        c.z = i1; c.w = -m[2 * d2 + 1] * i1;
        g_coef4[(r * (ND / 2) + d2) * NK + k] = c;
        logdet += logf(s0) + logf(s1);
    }
    g_c[id] = -logdet - 0.5f * ND * LOG_2PI;
}

__global__ void __launch_bounds__(THREADS) gauss_kernel(
        const float* __restrict__ x,
        const int* __restrict__ regions32,   // raw bits; dtype sniffed below
        float* __restrict__ out) {
    extern __shared__ float smem[];
    float* xs = smem;                         // [TB][NF] x tile
    int* reg_s = (int*)(smem + TB * NF);      // [NR*ND] region columns
    __shared__ int s_nonzero_odd;
    int tid = threadIdx.x;
    int b0 = blockIdx.x * TB;

    if (tid == 0) s_nonzero_odd = 0;
    __syncthreads();

    // Dtype sniff: if regions is int64 (little-endian, values < 1024), every
    // odd 32-bit word of the first NR*ND words is a zero hi-word. For genuine
    // int32 data, P(all 512 odd words == 0) ~ (1/1024)^512 ~ 0.
    {
        int nz = 0;
        for (int i = tid; i < NR * ND / 2; i += THREADS)
            nz |= regions32[2 * i + 1];
        if (nz) atomicOr(&s_nonzero_odd, 1);
    }
    __syncthreads();
    int is32 = s_nonzero_odd;                // 1 -> int32, 0 -> int64

    // Coalesced load of TB consecutive x rows into shared memory.
    {
        const float4* xg4 = (const float4*)(x + (size_t)b0 * NF);
        float4* xs4 = (float4*)xs;
        for (int i = tid; i < TB * NF / 4; i += THREADS)
            xs4[i] = xg4[i];
    }
    // Region index table -> int32, masked as crash insurance.
    for (int i = tid; i < NR * ND; i += THREADS) {
        int v = is32 ? regions32[i] : regions32[2 * i];
        reg_s[i] = v & (NF - 1);
    }
    __syncthreads();

    int w = tid >> 5, l = tid & 31;          // lane l == k
    const float* xr = xs + (size_t)(w * 4) * NF;  // 4 b-rows per warp

    for (int r = 0; r < NR; r++) {
        // Hoist this region's coefficients for my k into registers (9 LDG.128).
        float inv[ND], nmi[ND];
        const float4* cg = g_coef4 + r * (ND / 2) * NK + l;
#pragma unroll
        for (int d2 = 0; d2 < ND / 2; d2++) {
            float4 c = cg[d2 * NK];
            inv[2 * d2]     = c.x; nmi[2 * d2]     = c.y;
            inv[2 * d2 + 1] = c.z; nmi[2 * d2 + 1] = c.w;
        }
        float C = g_c[r * NK + l];

        float a0 = 0.f, a1 = 0.f, a2 = 0.f, a3 = 0.f;
        const int* rp = reg_s + r * ND;
#pragma unroll
        for (int d = 0; d < ND; d++) {
            int col = rp[d];                 // broadcast LDS
            const float* p = xr + col;       // immediate offsets cover the 4 rows
            float z0 = fmaf(p[0 * NF], inv[d], nmi[d]);
            float z1 = fmaf(p[1 * NF], inv[d], nmi[d]);
            float z2 = fmaf(p[2 * NF], inv[d], nmi[d]);
            float z3 = fmaf(p[3 * NF], inv[d], nmi[d]);
            a0 = fmaf(z0, z0, a0);
            a1 = fmaf(z1, z1, a1);
            a2 = fmaf(z2, z2, a2);
            a3 = fmaf(z3, z3, a3);
        }
        // out[b][r][k]: lanes are contiguous in k -> 128B coalesced stores.
        size_t ob = ((size_t)(b0 + w * 4) * NR + r) * NK + l;
        const size_t bs = (size_t)NR * NK;
        out[ob + 0 * bs] = fmaf(a0, -0.5f, C);
        out[ob + 1 * bs] = fmaf(a1, -0.5f, C);
        out[ob + 2 * bs] = fmaf(a2, -0.5f, C);
        out[ob + 3 * bs] = fmaf(a3, -0.5f, C);
    }
}

extern "C" void kernel_launch(void* const* d_in, const int* in_sizes, int n_in,
                              void* d_out, int out_size) {
    const float* x       = (const float*)d_in[0];
    const int* regions   = (const int*)d_in[1];   // int32 or int64 bits, sniffed
    const float* means   = (const float*)d_in[2];
    const float* scales  = (const float*)d_in[3];
    float* out = (float*)d_out;

    prep_kernel<<<(NR * NK + 255) / 256, 256>>>(means, scales);

    size_t smem = TB * NF * sizeof(float) + NR * ND * sizeof(int);  // 69632 B
    cudaFuncSetAttribute(gauss_kernel,
                         cudaFuncAttributeMaxDynamicSharedMemorySize, (int)smem);
    gauss_kernel<<<NB / TB, THREADS, smem>>>(x, regions, out);
}

// round 4
// speedup vs baseline: 1.7661x; 1.7661x over previous
#include <cuda_runtime.h>

#define NB 4096
#define NF 1024
#define NR 64
#define NK 32
#define ND 16
#define TB 16
#define THREADS 256
#define RSPLIT 2
#define RPB (NR / RSPLIT)
#define LOG_2PI 1.8378770664093453f

// Precomputed per-(r,k,d) coefficients:
//   inv = 1/scale, nmi = -mean/scale  packed as float4 {inv0,nmi0,inv1,nmi1}
//   layout [r][d/2][k] so lane k loads a float4 per 2 d's (coalesced 128B).
__device__ float4 g_coef4[NR * (ND / 2) * NK];
// g_c[r*K+k] = -(sum_d log scale) - 0.5*D*log(2pi)
__device__ float g_c[NR * NK];

__global__ void prep_kernel(const float* __restrict__ means,
                            const float* __restrict__ scales) {
    int id = blockIdx.x * blockDim.x + threadIdx.x;  // r*NK + k
    if (id >= NR * NK) return;
    int r = id / NK, k = id % NK;
    const float* m = means + (size_t)id * ND;
    const float* s = scales + (size_t)id * ND;
    float logdet = 0.f;
#pragma unroll
    for (int d2 = 0; d2 < ND / 2; d2++) {
        float s0 = s[2 * d2], s1 = s[2 * d2 + 1];
        float i0 = 1.0f / s0, i1 = 1.0f / s1;
        float4 c;
        c.x = i0; c.y = -m[2 * d2] * i0;
        c.z = i1; c.w = -m[2 * d2 + 1] * i1;
        g_coef4[(r * (ND / 2) + d2) * NK + k] = c;
        logdet += logf(s0) + logf(s1);
    }
    g_c[id] = -logdet - 0.5f * ND * LOG_2PI;
}

__global__ void __launch_bounds__(THREADS, 3) gauss_kernel(
        const float* __restrict__ x,
        const int* __restrict__ regions32,   // raw bits; dtype sniffed below
        float* __restrict__ out) {
    extern __shared__ float smem[];
    float* xs = smem;                         // [TB][NF] x tile
    int* reg_s = (int*)(smem + TB * NF);      // [RPB*ND] region columns
    __shared__ int s_nonzero_odd;
    int tid = threadIdx.x;
    int b0 = blockIdx.x * TB;
    int r0 = blockIdx.y * RPB;

    if (tid == 0) s_nonzero_odd = 0;
    __syncthreads();

    // Dtype sniff: regions may be int64 (little-endian, values < 1024) or
    // int32. If int64, every odd 32-bit word of the first 512 words is zero.
    {
        int nz = 0;
        for (int i = tid; i < 256; i += THREADS)
            nz |= regions32[2 * i + 1];
        if (nz) atomicOr(&s_nonzero_odd, 1);
    }
    __syncthreads();
    int is32 = s_nonzero_odd;                // 1 -> int32, 0 -> int64

    // Coalesced load of TB consecutive x rows into shared memory.
    {
        const float4* xg4 = (const float4*)(x + (size_t)b0 * NF);
        float4* xs4 = (float4*)xs;
        for (int i = tid; i < TB * NF / 4; i += THREADS)
            xs4[i] = xg4[i];
    }
    // Region index slice [r0, r0+RPB) -> int32, masked as crash insurance.
    for (int i = tid; i < RPB * ND; i += THREADS) {
        int g = r0 * ND + i;
        int v = is32 ? regions32[g] : regions32[2 * g];
        reg_s[i] = v & (NF - 1);
    }
    __syncthreads();

    int w = tid >> 5, l = tid & 31;          // lane l == k; warp has 2 b-rows
    const float* xr = xs + (size_t)(w * 2) * NF;

    for (int r = 0; r < RPB; r++) {
        int rr = r0 + r;
        const float4* cg = g_coef4 + rr * (ND / 2) * NK + l;
        float C = g_c[rr * NK + l];
        const int* rp = reg_s + r * ND;

        float a0 = 0.f, a1 = 0.f;
#pragma unroll
        for (int d2 = 0; d2 < ND / 2; d2++) {
            float4 c = cg[d2 * NK];          // {inv0,nmi0,inv1,nmi1} for my k
            int c0 = rp[2 * d2], c1 = rp[2 * d2 + 1];
            float z;
            z = fmaf(xr[c0],      c.x, c.y); a0 = fmaf(z, z, a0);
            z = fmaf(xr[NF + c0], c.x, c.y); a1 = fmaf(z, z, a1);
            z = fmaf(xr[c1],      c.z, c.w); a0 = fmaf(z, z, a0);
            z = fmaf(xr[NF + c1], c.z, c.w); a1 = fmaf(z, z, a1);
        }
        // out[b][r][k]: lanes contiguous in k -> 128B coalesced stores.
        size_t ob = ((size_t)(b0 + w * 2) * NR + rr) * NK + l;
        out[ob] = fmaf(a0, -0.5f, C);
        out[ob + (size_t)NR * NK] = fmaf(a1, -0.5f, C);
    }
}

extern "C" void kernel_launch(void* const* d_in, const int* in_sizes, int n_in,
                              void* d_out, int out_size) {
    const float* x       = (const float*)d_in[0];
    const int* regions   = (const int*)d_in[1];   // int32 or int64 bits, sniffed
    const float* means   = (const float*)d_in[2];
    const float* scales  = (const float*)d_in[3];
    float* out = (float*)d_out;

    prep_kernel<<<(NR * NK + 255) / 256, 256>>>(means, scales);

    size_t smem = TB * NF * sizeof(float) + RPB * ND * sizeof(int);  // 67584 B
    cudaFuncSetAttribute(gauss_kernel,
                         cudaFuncAttributeMaxDynamicSharedMemorySize, (int)smem);
    dim3 grid(NB / TB, RSPLIT);
    gauss_kernel<<<grid, THREADS, smem>>>(x, regions, out);
}

// round 6
// speedup vs baseline: 1.8977x; 1.0746x over previous
#include <cuda_runtime.h>

#define NB 4096
#define NF 1024
#define NR 64
#define NK 32
#define ND 16
#define TB 16
#define THREADS 256
#define RSPLIT 2
#define RPB (NR / RSPLIT)
#define LOG_2PI 1.8378770664093453f

typedef unsigned long long ull;

// Precomputed per-(r,k,d) coefficients:
//   inv = 1/scale, nmi = -mean/scale  packed as float4 {inv0,nmi0,inv1,nmi1}
//   layout [r][d/2][k] so lane k loads a float4 per 2 d's (coalesced LDG.128).
__device__ float4 g_coef4[NR * (ND / 2) * NK];
// g_c[r*K+k] = -(sum_d log scale) - 0.5*D*log(2pi)
__device__ float g_c[NR * NK];

__global__ void prep_kernel(const float* __restrict__ means,
                            const float* __restrict__ scales) {
    int id = blockIdx.x * blockDim.x + threadIdx.x;  // r*NK + k
    if (id >= NR * NK) return;
    int r = id / NK, k = id % NK;
    const float* m = means + (size_t)id * ND;
    const float* s = scales + (size_t)id * ND;
    float logdet = 0.f;
#pragma unroll
    for (int d2 = 0; d2 < ND / 2; d2++) {
        float s0 = s[2 * d2], s1 = s[2 * d2 + 1];
        float i0 = 1.0f / s0, i1 = 1.0f / s1;
        float4 c;
        c.x = i0; c.y = -m[2 * d2] * i0;
        c.z = i1; c.w = -m[2 * d2 + 1] * i1;
        g_coef4[(r * (ND / 2) + d2) * NK + k] = c;
        logdet += logf(s0) + logf(s1);
    }
    g_c[id] = -logdet - 0.5f * ND * LOG_2PI;
}

// -------- packed f32x2 helpers (FFMA2 path: PTX-only on sm_103a) --------
__device__ __forceinline__ ull pk2(float v) {          // {v, v}
    ull r; asm("mov.b64 %0, {%1, %1};" : "=l"(r) : "f"(v)); return r;
}
__device__ __forceinline__ ull fma2(ull a, ull b, ull c) {
    ull d; asm("fma.rn.f32x2 %0, %1, %2, %3;" : "=l"(d) : "l"(a), "l"(b), "l"(c));
    return d;
}
__device__ __forceinline__ ull add2(ull a, ull b) {
    ull d; asm("add.rn.f32x2 %0, %1, %2;" : "=l"(d) : "l"(a), "l"(b)); return d;
}
__device__ __forceinline__ void unpk2(ull v, float& lo, float& hi) {
    asm("mov.b64 {%0, %1}, %2;" : "=f"(lo), "=f"(hi) : "l"(v));
}

// Transposed pair-tile byte offset for column c, row-pair p:
//   64 B per column (8 pairs) + (c>>2)*8 pad so fill-phase STS.64 spreads
//   over all 16 bank-pairs (conflict-free); gather is broadcast -> free.
#define XT_BYTES (NF * 64 + (NF / 4) * 8)   // 67584

__global__ void __launch_bounds__(THREADS, 3) gauss_kernel(
        const float* __restrict__ x,
        const int* __restrict__ regions32,   // raw bits; dtype sniffed below
        float* __restrict__ out) {
    extern __shared__ char smem[];
    char* xt = smem;                               // transposed pair tile
    int* reg_s = (int*)(smem + XT_BYTES);          // [RPB*ND] pre-scaled offs
    __shared__ int s_nonzero_odd;
    int tid = threadIdx.x;
    int b0 = blockIdx.x * TB;
    int r0 = blockIdx.y * RPB;

    if (tid == 0) s_nonzero_odd = 0;
    __syncthreads();

    // Dtype sniff: regions may be int64 (little-endian, values < 1024) or
    // int32. If int64, every odd 32-bit word of the first 512 words is zero.
    {
        int nz = 0;
        for (int i = tid; i < 256; i += THREADS)
            nz |= regions32[2 * i + 1];
        if (nz) atomicOr(&s_nonzero_odd, 1);
    }
    __syncthreads();
    int is32 = s_nonzero_odd;                // 1 -> int32, 0 -> int64

    // Fill transposed pair tile: lanes take consecutive c (coalesced LDG),
    // each thread packs rows {2p, 2p+1} of column c into one float2.
    for (int i = tid; i < NF * (TB / 2); i += THREADS) {
        int c = i & (NF - 1);
        int p = i >> 10;                     // 0..7
        float lo = x[(size_t)(b0 + 2 * p) * NF + c];
        float hi = x[(size_t)(b0 + 2 * p + 1) * NF + c];
        int off = c * 64 + ((c >> 2) << 3) + (p << 3);
        *(float2*)(xt + off) = make_float2(lo, hi);
    }
    // Region index slice -> pre-scaled byte offsets P(c).
    for (int i = tid; i < RPB * ND; i += THREADS) {
        int g = r0 * ND + i;
        int v = is32 ? regions32[g] : regions32[2 * g];
        int c = v & (NF - 1);
        reg_s[i] = c * 64 + ((c >> 2) << 3);
    }
    __syncthreads();

    int w = tid >> 5, l = tid & 31;          // lane l == k; warp w owns pair p=w
    const char* xtw = xt + (w << 3);

    for (int r = 0; r < RPB; r++) {
        int rr = r0 + r;
        const float4* cg = g_coef4 + rr * (ND / 2) * NK + l;
        float C = g_c[rr * NK + l];
        const int4* rp4 = (const int4*)(reg_s + r * ND);

        ull ae = 0, ao = 0;                  // two packed accumulators
#pragma unroll
        for (int q = 0; q < 4; q++) {        // q covers d = 4q .. 4q+3
            int4 P = rp4[q];
            float4 c0 = cg[(2 * q) * NK];    // coefs for d = 4q, 4q+1
            float4 c1 = cg[(2 * q + 1) * NK];// coefs for d = 4q+2, 4q+3
            ull x0 = *(const ull*)(xtw + P.x);
            ull x1 = *(const ull*)(xtw + P.y);
            ull x2 = *(const ull*)(xtw + P.z);
            ull x3 = *(const ull*)(xtw + P.w);
            ull z;
            z = fma2(x0, pk2(c0.x), pk2(c0.y)); ae = fma2(z, z, ae);
            z = fma2(x1, pk2(c0.z), pk2(c0.w)); ao = fma2(z, z, ao);
            z = fma2(x2, pk2(c1.x), pk2(c1.y)); ae = fma2(z, z, ae);
            z = fma2(x3, pk2(c1.z), pk2(c1.w)); ao = fma2(z, z, ao);
        }
        ull a = add2(ae, ao);
        float s0, s1;
        unpk2(a, s0, s1);
        // out[b][r][k]: lanes contiguous in k -> coalesced 128B stores.
        size_t ob = ((size_t)(b0 + 2 * w) * NR + rr) * NK + l;
        out[ob] = fmaf(s0, -0.5f, C);
        out[ob + (size_t)NR * NK] = fmaf(s1, -0.5f, C);
    }
}

extern "C" void kernel_launch(void* const* d_in, const int* in_sizes, int n_in,
                              void* d_out, int out_size) {
    const float* x       = (const float*)d_in[0];
    const int* regions   = (const int*)d_in[1];   // int32 or int64 bits, sniffed
    const float* means   = (const float*)d_in[2];
    const float* scales  = (const float*)d_in[3];
    float* out = (float*)d_out;

    prep_kernel<<<(NR * NK + 255) / 256, 256>>>(means, scales);

    size_t smem = XT_BYTES + RPB * ND * sizeof(int);   // 69632 B
    cudaFuncSetAttribute(gauss_kernel,
                         cudaFuncAttributeMaxDynamicSharedMemorySize, (int)smem);
    dim3 grid(NB / TB, RSPLIT);
    gauss_kernel<<<grid, THREADS, smem>>>(x, regions, out);
}

// round 8
// speedup vs baseline: 3.3809x; 1.7816x over previous
#include <cuda_runtime.h>

#define NB 4096
#define NF 1024
#define NR 64
#define NK 32
#define ND 16
#define TB 16
#define THREADS 256
#define RSPLIT 2
#define RPB (NR / RSPLIT)
#define LOG_2PI 1.8378770664093453f

typedef unsigned long long ull;

// Precomputed per-(r,k,d) coefficients:
//   inv = 1/scale, nmi = -mean/scale  packed as float4 {inv0,nmi0,inv1,nmi1}
//   layout [r][d/2][k] so lane k loads a float4 per 2 d's (coalesced LDG.128).
__device__ float4 g_coef4[NR * (ND / 2) * NK];
// g_c[r*K+k] = -(sum_d log scale) - 0.5*D*log(2pi)
__device__ float g_c[NR * NK];

__global__ void prep_kernel(const float* __restrict__ means,
                            const float* __restrict__ scales) {
    int id = blockIdx.x * blockDim.x + threadIdx.x;  // r*NK + k
    if (id >= NR * NK) return;
    int r = id / NK, k = id % NK;
    const float* m = means + (size_t)id * ND;
    const float* s = scales + (size_t)id * ND;
    float logdet = 0.f;
#pragma unroll
    for (int d2 = 0; d2 < ND / 2; d2++) {
        float s0 = s[2 * d2], s1 = s[2 * d2 + 1];
        float i0 = 1.0f / s0, i1 = 1.0f / s1;
        float4 c;
        c.x = i0; c.y = -m[2 * d2] * i0;
        c.z = i1; c.w = -m[2 * d2 + 1] * i1;
        g_coef4[(r * (ND / 2) + d2) * NK + k] = c;
        logdet += logf(s0) + logf(s1);
    }
    g_c[id] = -logdet - 0.5f * ND * LOG_2PI;
}

// -------- packed f32x2 helpers (FFMA2 path: PTX-only on sm_103a) --------
__device__ __forceinline__ ull pk2(float v) {          // {v, v}
    ull r; asm("mov.b64 %0, {%1, %1};" : "=l"(r) : "f"(v)); return r;
}
__device__ __forceinline__ ull fma2(ull a, ull b, ull c) {
    ull d; asm("fma.rn.f32x2 %0, %1, %2, %3;" : "=l"(d) : "l"(a), "l"(b), "l"(c));
    return d;
}
__device__ __forceinline__ void unpk2(ull v, float& lo, float& hi) {
    asm("mov.b64 {%0, %1}, %2;" : "=f"(lo), "=f"(hi) : "l"(v));
}

// Transposed pair-tile byte offset for column c, row-pair p:
//   64 B per column (8 pairs) + (c>>2)*8 pad so fill-phase STS.64 spreads
//   over all 16 bank-pairs; hot-loop reads are lane-uniform broadcasts (N=1).
#define XT_BYTES (NF * 64 + (NF / 4) * 8)   // 67584

__global__ void __launch_bounds__(THREADS, 3) gauss_kernel(
        const float* __restrict__ x,
        const int* __restrict__ regions32,   // raw bits; dtype sniffed below
        float* __restrict__ out) {
    extern __shared__ char smem[];
    char* xt = smem;                               // transposed pair tile
    int* reg_s = (int*)(smem + XT_BYTES);          // [RPB*ND] pre-scaled offs
    __shared__ int s_nonzero_odd;
    int tid = threadIdx.x;
    int b0 = blockIdx.x * TB;
    int r0 = blockIdx.y * RPB;

    if (tid == 0) s_nonzero_odd = 0;
    __syncthreads();

    // Dtype sniff: regions may be int64 (little-endian, values < 1024) or
    // int32. If int64, every odd 32-bit word of the first 512 words is zero.
    {
        int nz = 0;
        for (int i = tid; i < 256; i += THREADS)
            nz |= regions32[2 * i + 1];
        if (nz) atomicOr(&s_nonzero_odd, 1);
    }
    __syncthreads();
    int is32 = s_nonzero_odd;                // 1 -> int32, 0 -> int64

    // Fill transposed pair tile: lanes take consecutive c (coalesced LDG),
    // each thread packs rows {2p, 2p+1} of column c into one float2.
    for (int i = tid; i < NF * (TB / 2); i += THREADS) {
        int c = i & (NF - 1);
        int p = i >> 10;                     // 0..7
        float lo = x[(size_t)(b0 + 2 * p) * NF + c];
        float hi = x[(size_t)(b0 + 2 * p + 1) * NF + c];
        int off = c * 64 + ((c >> 2) << 3) + (p << 3);
        *(float2*)(xt + off) = make_float2(lo, hi);
    }
    // Region index slice -> pre-scaled byte offsets P(c).
    for (int i = tid; i < RPB * ND; i += THREADS) {
        int g = r0 * ND + i;
        int v = is32 ? regions32[g] : regions32[2 * g];
        int c = v & (NF - 1);
        reg_s[i] = c * 64 + ((c >> 2) << 3);
    }
    __syncthreads();

    int w = tid >> 5, l = tid & 31;          // lane l == k
    // Each warp processes ALL 8 row-pairs of the tile for 4 regions.
    for (int i = 0; i < RPB / 8; i++) {
        int rloc = w * (RPB / 8) + i;
        int rr = r0 + rloc;
        const float4* cg = g_coef4 + rr * (ND / 2) * NK + l;
        float C = g_c[rr * NK + l];
        const int4* rp4 = (const int4*)(reg_s + rloc * ND);

        ull acc[8];
#pragma unroll
        for (int p = 0; p < 8; p++) acc[p] = 0;

#pragma unroll
        for (int q = 0; q < 4; q++) {        // q covers d = 4q .. 4q+3
            int4 P = rp4[q];
            float4 c0 = cg[(2 * q) * NK];    // coefs for d = 4q, 4q+1
            float4 c1 = cg[(2 * q + 1) * NK];// coefs for d = 4q+2, 4q+3
            ull i0 = pk2(c0.x), n0 = pk2(c0.y);
            ull i1 = pk2(c0.z), n1 = pk2(c0.w);
            ull i2 = pk2(c1.x), n2 = pk2(c1.y);
            ull i3 = pk2(c1.z), n3 = pk2(c1.w);
            const char* a0 = xt + P.x;       // lane-uniform bases; p*8 is an
            const char* a1 = xt + P.y;       // immediate in the LDS below
            const char* a2 = xt + P.z;
            const char* a3 = xt + P.w;
#pragma unroll
            for (int p = 0; p < 8; p++) {
                ull z;
                z = fma2(*(const ull*)(a0 + p * 8), i0, n0); acc[p] = fma2(z, z, acc[p]);
                z = fma2(*(const ull*)(a1 + p * 8), i1, n1); acc[p] = fma2(z, z, acc[p]);
                z = fma2(*(const ull*)(a2 + p * 8), i2, n2); acc[p] = fma2(z, z, acc[p]);
                z = fma2(*(const ull*)(a3 + p * 8), i3, n3); acc[p] = fma2(z, z, acc[p]);
            }
        }
        // out[b][r][k]: lanes contiguous in k -> coalesced 128B stores.
#pragma unroll
        for (int p = 0; p < 8; p++) {
            float s0, s1;
            unpk2(acc[p], s0, s1);
            size_t ob = ((size_t)(b0 + 2 * p) * NR + rr) * NK + l;
            out[ob] = fmaf(s0, -0.5f, C);
            out[ob + (size_t)NR * NK] = fmaf(s1, -0.5f, C);
        }
    }
}

extern "C" void kernel_launch(void* const* d_in, const int* in_sizes, int n_in,
                              void* d_out, int out_size) {
    const float* x       = (const float*)d_in[0];
    const int* regions   = (const int*)d_in[1];   // int32 or int64 bits, sniffed
    const float* means   = (const float*)d_in[2];
    const float* scales  = (const float*)d_in[3];
    float* out = (float*)d_out;

    prep_kernel<<<(NR * NK + 255) / 256, 256>>>(means, scales);

    size_t smem = XT_BYTES + RPB * ND * sizeof(int);   // 69632 B
    cudaFuncSetAttribute(gauss_kernel,
                         cudaFuncAttributeMaxDynamicSharedMemorySize, (int)smem);
    dim3 grid(NB / TB, RSPLIT);
    gauss_kernel<<<grid, THREADS, smem>>>(x, regions, out);
}